// round 11
// baseline (speedup 1.0000x reference)
#include <cuda_runtime.h>
#include <cuda_bf16.h>
#include <cstdint>

// ----------------------------------------------------------------------------
// TemporalEmbedding via precomputed tables.
//   out[o,b,l,:] = T01[i0*24+i1] + T2[i2] + Tp[l]
// Tables computed with mma.sync bf16 split-precision (3-term Markidis):
//   A@B ~= Ahi@Bhi + Ahi@Blo + Alo@Bhi   (fp32 accumulate)
// T01 is computed directly as a GEMM segment: A01 = concat(emb0[i], emb1[j])
// (K=1024) against W[0:1024], eliminating the separate combine kernel.
// Launch order: prep (all conversions, one launch) -> table_mma -> gather_add.
// ----------------------------------------------------------------------------

#define DMODEL 512
#define BATCH  32
#define PLEN   2048
#define NV4    (DMODEL / 4)

// g_Ahi/g_Alo rows: [0,2048) pe | [2048,2336) emb2 | [2336,2432) zero pad
#define AROWS  2432
// A01: 168 rows (pad 192) x 1024
#define A01ROWS 192

__device__ float g_T2 [288  * DMODEL];
__device__ float g_Tp [PLEN * DMODEL];
__device__ float g_T01[168  * DMODEL];
__device__ __nv_bfloat16 g_Ahi [AROWS * DMODEL];
__device__ __nv_bfloat16 g_Alo [AROWS * DMODEL];
__device__ __nv_bfloat16 g_A01hi[A01ROWS * 1024];
__device__ __nv_bfloat16 g_A01lo[A01ROWS * 1024];
__device__ __nv_bfloat16 g_Whi[DMODEL * 2048];   // [n][k], K-major rows
__device__ __nv_bfloat16 g_Wlo[DMODEL * 2048];

// ---------------------------------------------------------------- asm helpers
__device__ __forceinline__ uint32_t smem_u32(const void* p) {
    uint32_t a;
    asm("{ .reg .u64 t; cvta.to.shared.u64 t, %1; cvt.u32.u64 %0, t; }"
        : "=r"(a) : "l"(p));
    return a;
}

__device__ __forceinline__ void cp16(uint32_t dst, const void* src) {
    asm volatile("cp.async.cg.shared.global [%0], [%1], 16;"
                 :: "r"(dst), "l"(src));
}
#define CP_COMMIT() asm volatile("cp.async.commit_group;")

__device__ __forceinline__ void ldsm4(uint32_t* r, uint32_t addr) {
    asm volatile("ldmatrix.sync.aligned.m8n8.x4.shared.b16 {%0,%1,%2,%3}, [%4];"
                 : "=r"(r[0]), "=r"(r[1]), "=r"(r[2]), "=r"(r[3]) : "r"(addr));
}

__device__ __forceinline__ void mma16816(float* c, const uint32_t* a, const uint32_t* b) {
    asm volatile(
        "mma.sync.aligned.m16n8k16.row.col.f32.bf16.bf16.f32 "
        "{%0,%1,%2,%3}, {%4,%5,%6,%7}, {%8,%9}, {%0,%1,%2,%3};"
        : "+f"(c[0]), "+f"(c[1]), "+f"(c[2]), "+f"(c[3])
        : "r"(a[0]), "r"(a[1]), "r"(a[2]), "r"(a[3]), "r"(b[0]), "r"(b[1]));
}

__device__ __forceinline__ uint2 split_pack(float4 v) {
    __nv_bfloat16 hx = __float2bfloat16(v.x), hy = __float2bfloat16(v.y);
    __nv_bfloat16 hz = __float2bfloat16(v.z), hw = __float2bfloat16(v.w);
    uint2 p;
    p.x = (uint32_t)__bfloat16_as_ushort(hx) | ((uint32_t)__bfloat16_as_ushort(hy) << 16);
    p.y = (uint32_t)__bfloat16_as_ushort(hz) | ((uint32_t)__bfloat16_as_ushort(hw) << 16);
    return p;
}
__device__ __forceinline__ uint2 split_pack_lo(float4 v) {
    __nv_bfloat16 hx = __float2bfloat16(v.x), hy = __float2bfloat16(v.y);
    __nv_bfloat16 hz = __float2bfloat16(v.z), hw = __float2bfloat16(v.w);
    __nv_bfloat16 lx = __float2bfloat16(v.x - __bfloat162float(hx));
    __nv_bfloat16 ly = __float2bfloat16(v.y - __bfloat162float(hy));
    __nv_bfloat16 lz = __float2bfloat16(v.z - __bfloat162float(hz));
    __nv_bfloat16 lw = __float2bfloat16(v.w - __bfloat162float(hw));
    uint2 p;
    p.x = (uint32_t)__bfloat16_as_ushort(lx) | ((uint32_t)__bfloat16_as_ushort(ly) << 16);
    p.y = (uint32_t)__bfloat16_as_ushort(lz) | ((uint32_t)__bfloat16_as_ushort(lw) << 16);
    return p;
}

// ----------------------------------------------------------------------------
// prep: ONE launch for all conversions. 256 threads/block.
//  blocks [0,1024)        : conv_W 32x32 transpose tiles -> Whi/Wlo [n][k]
//  blocks [1024,2240)     : conv_A, 2 rows/block -> Ahi/Alo   (2432 rows)
//  blocks [2240,2432)     : conv_A01, 1 row/block -> A01hi/lo (192 rows x 1024)
// ----------------------------------------------------------------------------
__global__ __launch_bounds__(256) void prep(
    const float* __restrict__ W,    const float* __restrict__ pe,
    const float* __restrict__ emb2, const float* __restrict__ emb1,
    const float* __restrict__ emb0)
{
    __shared__ float tile[32][33];
    const int bx = blockIdx.x;

    if (bx < 1024) {
        // ---- conv_W: split-transpose W[2048,512] -> [n=512][k=2048]
        const int k0 = (bx & 63) * 32, n0 = (bx >> 6) * 32;
        const int tx = threadIdx.x & 31, ty = threadIdx.x >> 5;
        #pragma unroll
        for (int r = 0; r < 4; r++) {
            int i = ty + 8 * r;
            tile[i][tx] = W[(size_t)(k0 + i) * DMODEL + n0 + tx];
        }
        __syncthreads();
        #pragma unroll
        for (int r = 0; r < 4; r++) {
            int i = ty + 8 * r;                   // n_local
            float v = tile[tx][i];                // k_local = tx
            __nv_bfloat16 h = __float2bfloat16(v);
            __nv_bfloat16 l = __float2bfloat16(v - __bfloat162float(h));
            size_t o = (size_t)(n0 + i) * 2048 + k0 + tx;
            g_Whi[o] = h;
            g_Wlo[o] = l;
        }
    } else if (bx < 2240) {
        // ---- conv_A: rows of pe / emb2 (padded) -> Ahi/Alo
        const int pr = (bx - 1024) * 2 + (threadIdx.x >> 7);
        const int t  = threadIdx.x & 127;
        const float* src = nullptr;
        if (pr < 2048)      { src = pe + (size_t)pr * DMODEL; }
        else                { int r = pr - 2048; if (r < 288) src = emb2 + (size_t)r * DMODEL; }
        float4 v = src ? ((const float4*)src)[t] : make_float4(0.f, 0.f, 0.f, 0.f);
        ((uint2*)g_Ahi)[(size_t)pr * NV4 + t] = split_pack(v);
        ((uint2*)g_Alo)[(size_t)pr * NV4 + t] = split_pack_lo(v);
    } else {
        // ---- conv_A01: row r = concat(emb0[r/24], emb1[r%24]) over K=1024
        const int r = bx - 2240;                  // 0..191
        const int c = threadIdx.x;                // float4 lane 0..255
        float4 v = make_float4(0.f, 0.f, 0.f, 0.f);
        if (r < 168) {
            const int i = r / 24, j = r % 24;
            v = (c < 128) ? ((const float4*)(emb0 + (size_t)i * DMODEL))[c]
                          : ((const float4*)(emb1 + (size_t)j * DMODEL))[c - 128];
        }
        ((uint2*)g_A01hi)[(size_t)r * 256 + c] = split_pack(v);
        ((uint2*)g_A01lo)[(size_t)r * 256 + c] = split_pack_lo(v);
    }
}

// ----------------------------------------------------------------------------
// table_mma: mma.sync bf16x3 GEMM for all three tables.
// grid (41 m-blocks, 8 n-tiles), 128 threads. CTA tile 64(M) x 64(N).
//  blocks  0..31 : Tp  (K=512,  koff=1536, +bias)
//  blocks 32..37 : T2  (K=512,  koff=1024)
//  blocks 38..40 : T01 (K=1024, koff=0)
// Virtual K = 3 terms x K, streamed as k32 stages through a 3-deep cp.async
// pipeline; 80B-padded smem rows (conflict-free ldmatrix); 2x2 warp layout.
// ----------------------------------------------------------------------------
#define ROWB   80
#define OPBYTES (64 * ROWB)          // 5120 per operand per stage
#define NSTAGE 3

__global__ __launch_bounds__(128) void table_mma(const float* __restrict__ bias)
{
    __shared__ __align__(16) char sm[NSTAGE * 2 * OPBYTES];   // 30720 B
    const uint32_t sbase = smem_u32(sm);

    const int tid = threadIdx.x;
    const int bx = blockIdx.x, by = blockIdx.y;
    const int col0 = by * 64;

    const __nv_bfloat16 *Ahip, *Alop;
    float* C; int M, arow0, astride, koff, kshift; bool addb = false;
    if (bx < 32) {
        Ahip = g_Ahi;   Alop = g_Alo;   C = g_Tp;  M = 2048;
        arow0 = bx * 64;        astride = 512;  koff = 1536; kshift = 4; addb = true;
    } else if (bx < 38) {
        Ahip = g_Ahi;   Alop = g_Alo;   C = g_T2;  M = 288;
        arow0 = (bx - 32) * 64; astride = 512;  koff = 1024; kshift = 4;
        // A rows for T2 live at offset 2048 in g_Ahi
        Ahip += (size_t)2048 * DMODEL;  Alop += (size_t)2048 * DMODEL;
    } else {
        Ahip = g_A01hi; Alop = g_A01lo; C = g_T01; M = 168;
        arow0 = (bx - 38) * 64; astride = 1024; koff = 0;    kshift = 5;
    }
    const int kmask = (1 << kshift) - 1;
    const int NKSv  = 3 << kshift;               // 48 or 96 k32 stages

    // per-thread cp.async geometry: rows tid>>2 and +32, quarter q = tid&3
    const int rA = tid >> 2;
    const int q  = tid & 3;
    const uint32_t dA0 = rA * ROWB + q * 16;
    const uint32_t dA1 = (rA + 32) * ROWB + q * 16;
    const size_t aoff0 = (size_t)(arow0 + rA) * astride + q * 8;
    const size_t aoff1 = aoff0 + (size_t)32 * astride;
    const size_t boff0 = (size_t)(col0 + rA) * 2048 + koff + q * 8;
    const size_t boff1 = boff0 + (size_t)32 * 2048;

    // warp / lane geometry
    const int wid  = tid >> 5, lane = tid & 31;
    const int wm   = (wid & 1) * 32, wn = (wid >> 1) * 32;
    const int quad = lane >> 3, lr = lane & 7;

    uint32_t offA[2], offB[2];
    #pragma unroll
    for (int mf = 0; mf < 2; mf++)
        offA[mf] = (uint32_t)(wm + mf * 16 + (quad & 1) * 8 + lr) * ROWB + (quad >> 1) * 16;
    #pragma unroll
    for (int nb = 0; nb < 2; nb++)
        offB[nb] = (uint32_t)(wn + nb * 16 + ((quad >> 1) & 1) * 8 + lr) * ROWB + (quad & 1) * 16;

    float acc[2][4][4] = {};

    // ---- stage issue: stage s -> term s>>kshift, k0 = (s&kmask)*32, buf s%3
    auto issue = [&](int s) {
        const int term = s >> kshift;
        const int k0   = (s & kmask) * 32;
        const __nv_bfloat16* Asrc = (term == 2) ? Alop  : Ahip;
        const __nv_bfloat16* Bsrc = (term == 1) ? g_Wlo : g_Whi;
        const uint32_t sA = sbase + (uint32_t)(s % NSTAGE) * (2 * OPBYTES);
        const uint32_t sB = sA + OPBYTES;
        cp16(sA + dA0, Asrc + aoff0 + k0);
        cp16(sA + dA1, Asrc + aoff1 + k0);
        cp16(sB + dA0, Bsrc + boff0 + k0);
        cp16(sB + dA1, Bsrc + boff1 + k0);
        CP_COMMIT();
    };

    issue(0);
    issue(1);

    for (int s = 0; s < NKSv; s++) {
        if (s + 2 < NKSv) {
            issue(s + 2);
            asm volatile("cp.async.wait_group 2;");
        } else {
            asm volatile("cp.async.wait_group 0;");
        }
        __syncthreads();

        const uint32_t sA = sbase + (uint32_t)(s % NSTAGE) * (2 * OPBYTES);
        const uint32_t sB = sA + OPBYTES;

        #pragma unroll
        for (int kh = 0; kh < 2; kh++) {          // two k16 steps per k32 stage
            uint32_t a[2][4], b[2][4];
            ldsm4(a[0], sA + offA[0] + kh * 32);
            ldsm4(a[1], sA + offA[1] + kh * 32);
            ldsm4(b[0], sB + offB[0] + kh * 32);
            ldsm4(b[1], sB + offB[1] + kh * 32);
            #pragma unroll
            for (int mf = 0; mf < 2; mf++) {
                mma16816(acc[mf][0], a[mf], &b[0][0]);
                mma16816(acc[mf][1], a[mf], &b[0][2]);
                mma16816(acc[mf][2], a[mf], &b[1][0]);
                mma16816(acc[mf][3], a[mf], &b[1][2]);
            }
        }
        __syncthreads();
    }

    // ---- epilogue
    const int erow = lane >> 2;
    const int ecol = (lane & 3) * 2;

    float2 bb[4];
    #pragma unroll
    for (int nf = 0; nf < 4; nf++) {
        if (addb) {
            const int n = col0 + wn + nf * 8 + ecol;
            bb[nf].x = bias[n];
            bb[nf].y = bias[n + 1];
        } else {
            bb[nf].x = 0.f; bb[nf].y = 0.f;
        }
    }

    #pragma unroll
    for (int mf = 0; mf < 2; mf++) {
        const int m0 = arow0 + wm + mf * 16 + erow;
        #pragma unroll
        for (int nf = 0; nf < 4; nf++) {
            const int n = col0 + wn + nf * 8 + ecol;
            if (m0 < M) {
                float2 v = make_float2(acc[mf][nf][0] + bb[nf].x,
                                       acc[mf][nf][1] + bb[nf].y);
                *(float2*)&C[(size_t)m0 * DMODEL + n] = v;
            }
            if (m0 + 8 < M) {
                float2 v = make_float2(acc[mf][nf][2] + bb[nf].x,
                                       acc[mf][nf][3] + bb[nf].y);
                *(float2*)&C[(size_t)(m0 + 8) * DMODEL + n] = v;
            }
        }
    }
}

// ----------------------------------------------------------------------------
// gather_add: out = T01 + T2 + Tp.  grid (2048, 2), 128 threads.
// ----------------------------------------------------------------------------
__global__ __launch_bounds__(128) void gather_add(
    const int* __restrict__ in0, const int* __restrict__ tg0,
    const int* __restrict__ in1, const int* __restrict__ tg1,
    const int* __restrict__ in2, const int* __restrict__ tg2,
    float* __restrict__ out)
{
    const int l = blockIdx.x, o = blockIdx.y, t = threadIdx.x;

    __shared__ int sidx[3][BATCH];
    if (t < 96) {
        int which = t >> 5, b = t & 31;
        const int* p = (which == 0) ? (o ? tg0 : in0)
                     : (which == 1) ? (o ? tg1 : in1)
                                    : (o ? tg2 : in2);
        sidx[which][b] = p[b * PLEN + l];
    }
    __syncthreads();

    const float4* __restrict__ T01 = (const float4*)g_T01;
    const float4* __restrict__ T2  = (const float4*)g_T2;
    const float4 tp = ((const float4*)g_Tp)[l * NV4 + t];

    float4* o4 = (float4*)out + ((size_t)o * BATCH * PLEN + l) * NV4 + t;

    #pragma unroll 4
    for (int b = 0; b < BATCH; b++) {
        const int i01 = sidx[0][b] * 24 + sidx[1][b];
        const int i2  = sidx[2][b];
        float4 a = T01[i01 * NV4 + t];
        float4 d = T2 [i2  * NV4 + t];
        float4 v;
        v.x = tp.x + a.x + d.x;
        v.y = tp.y + a.y + d.y;
        v.z = tp.z + a.z + d.z;
        v.w = tp.w + a.w + d.w;
        __stcs(o4 + (size_t)b * PLEN * NV4, v);
    }
}

// ----------------------------------------------------------------------------
// Launch. Inputs (metadata order):
//  0..5: in0,tg0,in1,tg1,in2,tg2 int32 [32,2048]
//  6:emb0[7,512] 7:emb1[24,512] 8:emb2[288,512] 9:pe[4096,512]
//  10:W[2048,512] 11:b[512]       output: float32 [2,32,2048,512]
// ----------------------------------------------------------------------------
extern "C" void kernel_launch(void* const* d_in, const int* in_sizes, int n_in,
                              void* d_out, int out_size)
{
    const int*   in0  = (const int*)  d_in[0];
    const int*   tg0  = (const int*)  d_in[1];
    const int*   in1  = (const int*)  d_in[2];
    const int*   tg1  = (const int*)  d_in[3];
    const int*   in2  = (const int*)  d_in[4];
    const int*   tg2  = (const int*)  d_in[5];
    const float* emb0 = (const float*)d_in[6];
    const float* emb1 = (const float*)d_in[7];
    const float* emb2 = (const float*)d_in[8];
    const float* pe   = (const float*)d_in[9];
    const float* W    = (const float*)d_in[10];
    const float* bias = (const float*)d_in[11];
    float* out = (float*)d_out;

    prep<<<2432, 256>>>(W, pe, emb2, emb1, emb0);
    table_mma<<<dim3(41, 8), 128>>>(bias);
    gather_add<<<dim3(PLEN, 2), 128>>>(in0, tg0, in1, tg1, in2, tg2, out);
}

// round 12
// speedup vs baseline: 1.1746x; 1.1746x over previous
#include <cuda_runtime.h>
#include <cuda_bf16.h>
#include <cstdint>

// ----------------------------------------------------------------------------
// TemporalEmbedding via precomputed tables.
//   out[o,b,l,:] = T01[i0*24+i1] + T2[i2] + Tp[l]
// Tables via mma.sync bf16 split-precision (3-term Markidis):
//   A@B ~= Ahi@Bhi + Ahi@Blo + Alo@Bhi   (fp32 accumulate)
// Split-K/split-term: every mma CTA does exactly K=512 (16 k32 stages) of one
// precision term; contributions combined with atomicAdd into zeroed tables.
// Launch order: prep (conversions + table zeroing) -> table_mma -> gather_add.
// ----------------------------------------------------------------------------

#define DMODEL 512
#define BATCH  32
#define PLEN   2048
#define NV4    (DMODEL / 4)

// g_Ahi/g_Alo rows: [0,2048) pe | [2048,2336) emb2 | [2336,2432) zero pad
#define AROWS   2432
#define A01ROWS 192          // 168 used, pad to 3*64

__device__ float g_T2 [288  * DMODEL];
__device__ float g_Tp [PLEN * DMODEL];
__device__ float g_T01[168  * DMODEL];
__device__ __nv_bfloat16 g_Ahi [AROWS * DMODEL];
__device__ __nv_bfloat16 g_Alo [AROWS * DMODEL];
__device__ __nv_bfloat16 g_A01hi[A01ROWS * 1024];
__device__ __nv_bfloat16 g_A01lo[A01ROWS * 1024];
__device__ __nv_bfloat16 g_Whi[DMODEL * 2048];   // [n][k], K-major rows
__device__ __nv_bfloat16 g_Wlo[DMODEL * 2048];

// ---------------------------------------------------------------- asm helpers
__device__ __forceinline__ uint32_t smem_u32(const void* p) {
    uint32_t a;
    asm("{ .reg .u64 t; cvta.to.shared.u64 t, %1; cvt.u32.u64 %0, t; }"
        : "=r"(a) : "l"(p));
    return a;
}

__device__ __forceinline__ void cp16(uint32_t dst, const void* src) {
    asm volatile("cp.async.cg.shared.global [%0], [%1], 16;"
                 :: "r"(dst), "l"(src));
}
#define CP_COMMIT() asm volatile("cp.async.commit_group;")

__device__ __forceinline__ void ldsm4(uint32_t* r, uint32_t addr) {
    asm volatile("ldmatrix.sync.aligned.m8n8.x4.shared.b16 {%0,%1,%2,%3}, [%4];"
                 : "=r"(r[0]), "=r"(r[1]), "=r"(r[2]), "=r"(r[3]) : "r"(addr));
}

__device__ __forceinline__ void mma16816(float* c, const uint32_t* a, const uint32_t* b) {
    asm volatile(
        "mma.sync.aligned.m16n8k16.row.col.f32.bf16.bf16.f32 "
        "{%0,%1,%2,%3}, {%4,%5,%6,%7}, {%8,%9}, {%0,%1,%2,%3};"
        : "+f"(c[0]), "+f"(c[1]), "+f"(c[2]), "+f"(c[3])
        : "r"(a[0]), "r"(a[1]), "r"(a[2]), "r"(a[3]), "r"(b[0]), "r"(b[1]));
}

__device__ __forceinline__ uint2 split_pack(float4 v) {
    __nv_bfloat16 hx = __float2bfloat16(v.x), hy = __float2bfloat16(v.y);
    __nv_bfloat16 hz = __float2bfloat16(v.z), hw = __float2bfloat16(v.w);
    uint2 p;
    p.x = (uint32_t)__bfloat16_as_ushort(hx) | ((uint32_t)__bfloat16_as_ushort(hy) << 16);
    p.y = (uint32_t)__bfloat16_as_ushort(hz) | ((uint32_t)__bfloat16_as_ushort(hw) << 16);
    return p;
}
__device__ __forceinline__ uint2 split_pack_lo(float4 v) {
    __nv_bfloat16 hx = __float2bfloat16(v.x), hy = __float2bfloat16(v.y);
    __nv_bfloat16 hz = __float2bfloat16(v.z), hw = __float2bfloat16(v.w);
    __nv_bfloat16 lx = __float2bfloat16(v.x - __bfloat162float(hx));
    __nv_bfloat16 ly = __float2bfloat16(v.y - __bfloat162float(hy));
    __nv_bfloat16 lz = __float2bfloat16(v.z - __bfloat162float(hz));
    __nv_bfloat16 lw = __float2bfloat16(v.w - __bfloat162float(hw));
    uint2 p;
    p.x = (uint32_t)__bfloat16_as_ushort(lx) | ((uint32_t)__bfloat16_as_ushort(ly) << 16);
    p.y = (uint32_t)__bfloat16_as_ushort(lz) | ((uint32_t)__bfloat16_as_ushort(lw) << 16);
    return p;
}

// ----------------------------------------------------------------------------
// prep: ONE launch for all conversions + zeroing of accumulator tables.
//  blocks [0,1024)     : conv_W 32x32 transpose tiles -> Whi/Wlo [n][k]
//  blocks [1024,2240)  : conv_A, 2 rows/block -> Ahi/Alo
//  blocks [2240,2432)  : conv_A01, 1 row/block -> A01hi/lo
//  blocks [2432,2752)  : zero g_Tp / g_T2 / g_T01 (graph-replay safe)
// ----------------------------------------------------------------------------
#define NZ_TP  (PLEN * DMODEL / 4)   // 262144 float4
#define NZ_T2  (288  * DMODEL / 4)   //  36864
#define NZ_T01 (168  * DMODEL / 4)   //  21504
#define NZ_ALL (NZ_TP + NZ_T2 + NZ_T01)     // 320512
#define PREP_GRID (2432 + 320)

__global__ __launch_bounds__(256) void prep(
    const float* __restrict__ W,    const float* __restrict__ pe,
    const float* __restrict__ emb2, const float* __restrict__ emb1,
    const float* __restrict__ emb0)
{
    __shared__ float tile[32][33];
    const int bx = blockIdx.x;

    if (bx < 1024) {
        // ---- conv_W: split-transpose W[2048,512] -> [n=512][k=2048]
        const int k0 = (bx & 63) * 32, n0 = (bx >> 6) * 32;
        const int tx = threadIdx.x & 31, ty = threadIdx.x >> 5;
        #pragma unroll
        for (int r = 0; r < 4; r++) {
            int i = ty + 8 * r;
            tile[i][tx] = W[(size_t)(k0 + i) * DMODEL + n0 + tx];
        }
        __syncthreads();
        #pragma unroll
        for (int r = 0; r < 4; r++) {
            int i = ty + 8 * r;                   // n_local
            float v = tile[tx][i];                // k_local = tx
            __nv_bfloat16 h = __float2bfloat16(v);
            __nv_bfloat16 l = __float2bfloat16(v - __bfloat162float(h));
            size_t o = (size_t)(n0 + i) * 2048 + k0 + tx;
            g_Whi[o] = h;
            g_Wlo[o] = l;
        }
    } else if (bx < 2240) {
        // ---- conv_A: rows of pe / emb2 (padded) -> Ahi/Alo
        const int pr = (bx - 1024) * 2 + (threadIdx.x >> 7);
        const int t  = threadIdx.x & 127;
        const float* src = nullptr;
        if (pr < 2048)      { src = pe + (size_t)pr * DMODEL; }
        else                { int r = pr - 2048; if (r < 288) src = emb2 + (size_t)r * DMODEL; }
        float4 v = src ? ((const float4*)src)[t] : make_float4(0.f, 0.f, 0.f, 0.f);
        ((uint2*)g_Ahi)[(size_t)pr * NV4 + t] = split_pack(v);
        ((uint2*)g_Alo)[(size_t)pr * NV4 + t] = split_pack_lo(v);
    } else if (bx < 2432) {
        // ---- conv_A01: row r = concat(emb0[r/24], emb1[r%24]) over K=1024
        const int r = bx - 2240;                  // 0..191
        const int c = threadIdx.x;                // float4 lane 0..255
        float4 v = make_float4(0.f, 0.f, 0.f, 0.f);
        if (r < 168) {
            const int i = r / 24, j = r % 24;
            v = (c < 128) ? ((const float4*)(emb0 + (size_t)i * DMODEL))[c]
                          : ((const float4*)(emb1 + (size_t)j * DMODEL))[c - 128];
        }
        ((uint2*)g_A01hi)[(size_t)r * 256 + c] = split_pack(v);
        ((uint2*)g_A01lo)[(size_t)r * 256 + c] = split_pack_lo(v);
    } else {
        // ---- zero accumulator tables (4 float4 per thread)
        const float4 z = make_float4(0.f, 0.f, 0.f, 0.f);
        const int base = ((bx - 2432) * 256 + threadIdx.x) * 4;
        #pragma unroll
        for (int u = 0; u < 4; u++) {
            int i = base + u;
            if (i < NZ_TP)            ((float4*)g_Tp )[i] = z;
            else if (i < NZ_TP + NZ_T2)      ((float4*)g_T2 )[i - NZ_TP] = z;
            else if (i < NZ_ALL)     ((float4*)g_T01)[i - NZ_TP - NZ_T2] = z;
        }
    }
}

// ----------------------------------------------------------------------------
// table_mma: uniform split-K/split-term bf16 MMA.
// grid (132, 8): bx = term*44 + unit ; 128 threads; CTA tile 64(M) x 64(N),
// exactly 16 k32 stages (K=512) per CTA. Results via atomicAdd (tables are
// zeroed in prep). Bias added by term-0 Tp CTAs only.
//  unit  0..31 : Tp  (K-rows 1536..2047 of W)
//  unit 32..37 : T2  (K-rows 1024..1535)
//  unit 38..43 : T01 (h = unit-38: m = h>>1, khalf = h&1 -> K-rows 0..1023)
// ----------------------------------------------------------------------------
#define ROWB   80
#define OPBYTES (64 * ROWB)          // 5120 per operand per stage
#define NSTAGE 3
#define NKS    16

__global__ __launch_bounds__(128) void table_mma(const float* __restrict__ bias)
{
    __shared__ __align__(16) char sm[NSTAGE * 2 * OPBYTES];   // 30720 B
    const uint32_t sbase = smem_u32(sm);

    const int tid = threadIdx.x;
    const int bx = blockIdx.x, by = blockIdx.y;
    const int col0 = by * 64;
    const int term = bx / 44;
    const int unit = bx - term * 44;

    const __nv_bfloat16 *Ahip, *Alop;
    float* C; int M, arow0, astride, koffB, koffA; bool addb = false;
    if (unit < 32) {
        Ahip = g_Ahi;   Alop = g_Alo;   C = g_Tp;  M = 2048;
        arow0 = unit * 64;        astride = 512;  koffB = 1536; koffA = 0;
        addb = (term == 0);
    } else if (unit < 38) {
        Ahip = g_Ahi + (size_t)2048 * DMODEL;
        Alop = g_Alo + (size_t)2048 * DMODEL;
        C = g_T2;  M = 288;
        arow0 = (unit - 32) * 64; astride = 512;  koffB = 1024; koffA = 0;
    } else {
        const int h = unit - 38;                  // 0..5
        Ahip = g_A01hi; Alop = g_A01lo; C = g_T01; M = 168;
        arow0 = (h >> 1) * 64;    astride = 1024;
        koffB = (h & 1) * 512;    koffA = (h & 1) * 512;
    }

    const __nv_bfloat16* Asrc = (term == 2) ? Alop  : Ahip;
    const __nv_bfloat16* Bsrc = (term == 1) ? g_Wlo : g_Whi;

    // per-thread cp.async geometry: rows tid>>2 and +32, quarter q = tid&3
    const int rA = tid >> 2;
    const int q  = tid & 3;
    const uint32_t dA0 = rA * ROWB + q * 16;
    const uint32_t dA1 = (rA + 32) * ROWB + q * 16;
    const __nv_bfloat16* pa0 = Asrc + (size_t)(arow0 + rA) * astride + koffA + q * 8;
    const __nv_bfloat16* pa1 = pa0 + (size_t)32 * astride;
    const __nv_bfloat16* pb0 = Bsrc + (size_t)(col0 + rA) * 2048 + koffB + q * 8;
    const __nv_bfloat16* pb1 = pb0 + (size_t)32 * 2048;

    // warp / lane geometry
    const int wid  = tid >> 5, lane = tid & 31;
    const int wm   = (wid & 1) * 32, wn = (wid >> 1) * 32;
    const int quad = lane >> 3, lr = lane & 7;

    uint32_t offA[2], offB[2];
    #pragma unroll
    for (int mf = 0; mf < 2; mf++)
        offA[mf] = (uint32_t)(wm + mf * 16 + (quad & 1) * 8 + lr) * ROWB + (quad >> 1) * 16;
    #pragma unroll
    for (int nb = 0; nb < 2; nb++)
        offB[nb] = (uint32_t)(wn + nb * 16 + ((quad >> 1) & 1) * 8 + lr) * ROWB + (quad & 1) * 16;

    float acc[2][4][4] = {};

    auto issue = [&](int s) {
        const int k0 = s * 32;
        const uint32_t sA = sbase + (uint32_t)(s % NSTAGE) * (2 * OPBYTES);
        const uint32_t sB = sA + OPBYTES;
        cp16(sA + dA0, pa0 + k0);
        cp16(sA + dA1, pa1 + k0);
        cp16(sB + dA0, pb0 + k0);
        cp16(sB + dA1, pb1 + k0);
        CP_COMMIT();
    };

    issue(0);
    issue(1);

    for (int s = 0; s < NKS; s++) {
        if (s + 2 < NKS) {
            issue(s + 2);
            asm volatile("cp.async.wait_group 2;");
        } else {
            asm volatile("cp.async.wait_group 0;");
        }
        __syncthreads();

        const uint32_t sA = sbase + (uint32_t)(s % NSTAGE) * (2 * OPBYTES);
        const uint32_t sB = sA + OPBYTES;

        #pragma unroll
        for (int kh = 0; kh < 2; kh++) {          // two k16 steps per k32 stage
            uint32_t a[2][4], b[2][4];
            ldsm4(a[0], sA + offA[0] + kh * 32);
            ldsm4(a[1], sA + offA[1] + kh * 32);
            ldsm4(b[0], sB + offB[0] + kh * 32);
            ldsm4(b[1], sB + offB[1] + kh * 32);
            #pragma unroll
            for (int mf = 0; mf < 2; mf++) {
                mma16816(acc[mf][0], a[mf], &b[0][0]);
                mma16816(acc[mf][1], a[mf], &b[0][2]);
                mma16816(acc[mf][2], a[mf], &b[1][0]);
                mma16816(acc[mf][3], a[mf], &b[1][2]);
            }
        }
        __syncthreads();
    }

    // ---- epilogue: atomic accumulate (REDG); bias once via term-0 Tp CTAs
    const int erow = lane >> 2;
    const int ecol = (lane & 3) * 2;

    float2 bb[4];
    #pragma unroll
    for (int nf = 0; nf < 4; nf++) {
        if (addb) {
            const int n = col0 + wn + nf * 8 + ecol;
            bb[nf].x = bias[n];
            bb[nf].y = bias[n + 1];
        } else {
            bb[nf].x = 0.f; bb[nf].y = 0.f;
        }
    }

    #pragma unroll
    for (int mf = 0; mf < 2; mf++) {
        const int m0 = arow0 + wm + mf * 16 + erow;
        #pragma unroll
        for (int nf = 0; nf < 4; nf++) {
            const int n = col0 + wn + nf * 8 + ecol;
            if (m0 < M) {
                float* p = &C[(size_t)m0 * DMODEL + n];
                atomicAdd(p,     acc[mf][nf][0] + bb[nf].x);
                atomicAdd(p + 1, acc[mf][nf][1] + bb[nf].y);
            }
            if (m0 + 8 < M) {
                float* p = &C[(size_t)(m0 + 8) * DMODEL + n];
                atomicAdd(p,     acc[mf][nf][2] + bb[nf].x);
                atomicAdd(p + 1, acc[mf][nf][3] + bb[nf].y);
            }
        }
    }
}

// ----------------------------------------------------------------------------
// gather_add: out = T01 + T2 + Tp.  grid (2048, 2), 128 threads.
// ----------------------------------------------------------------------------
__global__ __launch_bounds__(128) void gather_add(
    const int* __restrict__ in0, const int* __restrict__ tg0,
    const int* __restrict__ in1, const int* __restrict__ tg1,
    const int* __restrict__ in2, const int* __restrict__ tg2,
    float* __restrict__ out)
{
    const int l = blockIdx.x, o = blockIdx.y, t = threadIdx.x;

    __shared__ int sidx[3][BATCH];
    if (t < 96) {
        int which = t >> 5, b = t & 31;
        const int* p = (which == 0) ? (o ? tg0 : in0)
                     : (which == 1) ? (o ? tg1 : in1)
                                    : (o ? tg2 : in2);
        sidx[which][b] = p[b * PLEN + l];
    }
    __syncthreads();

    const float4* __restrict__ T01 = (const float4*)g_T01;
    const float4* __restrict__ T2  = (const float4*)g_T2;
    const float4 tp = ((const float4*)g_Tp)[l * NV4 + t];

    float4* o4 = (float4*)out + ((size_t)o * BATCH * PLEN + l) * NV4 + t;

    #pragma unroll 4
    for (int b = 0; b < BATCH; b++) {
        const int i01 = sidx[0][b] * 24 + sidx[1][b];
        const int i2  = sidx[2][b];
        float4 a = T01[i01 * NV4 + t];
        float4 d = T2 [i2  * NV4 + t];
        float4 v;
        v.x = tp.x + a.x + d.x;
        v.y = tp.y + a.y + d.y;
        v.z = tp.z + a.z + d.z;
        v.w = tp.w + a.w + d.w;
        __stcs(o4 + (size_t)b * PLEN * NV4, v);
    }
}

// ----------------------------------------------------------------------------
// Launch. Inputs (metadata order):
//  0..5: in0,tg0,in1,tg1,in2,tg2 int32 [32,2048]
//  6:emb0[7,512] 7:emb1[24,512] 8:emb2[288,512] 9:pe[4096,512]
//  10:W[2048,512] 11:b[512]       output: float32 [2,32,2048,512]
// ----------------------------------------------------------------------------
extern "C" void kernel_launch(void* const* d_in, const int* in_sizes, int n_in,
                              void* d_out, int out_size)
{
    const int*   in0  = (const int*)  d_in[0];
    const int*   tg0  = (const int*)  d_in[1];
    const int*   in1  = (const int*)  d_in[2];
    const int*   tg1  = (const int*)  d_in[3];
    const int*   in2  = (const int*)  d_in[4];
    const int*   tg2  = (const int*)  d_in[5];
    const float* emb0 = (const float*)d_in[6];
    const float* emb1 = (const float*)d_in[7];
    const float* emb2 = (const float*)d_in[8];
    const float* pe   = (const float*)d_in[9];
    const float* W    = (const float*)d_in[10];
    const float* bias = (const float*)d_in[11];
    float* out = (float*)d_out;

    prep<<<PREP_GRID, 256>>>(W, pe, emb2, emb1, emb0);
    table_mma<<<dim3(132, 8), 128>>>(bias);
    gather_add<<<dim3(PLEN, 2), 128>>>(in0, tg0, in1, tg1, in2, tg2, out);
}

// round 13
// speedup vs baseline: 1.1995x; 1.0212x over previous
#include <cuda_runtime.h>
#include <cuda_bf16.h>
#include <cstdint>

// ----------------------------------------------------------------------------
// TemporalEmbedding via precomputed tables.
//   out[o,b,l,:] = T01[i0*24+i1] + T2[i2] + Tp[l]
// Tables via mma.sync bf16 split-precision (3-term Markidis):
//   A@B ~= Ahi@Bhi + Ahi@Blo + Alo@Bhi   (fp32 accumulate)
// Split-K/split-term: every mma CTA does exactly K=512 (16 k32 stages) of one
// precision term; contributions combined with red.global.add.v2.f32 into
// tables zeroed by prep.
// Launch order: prep (conversions + zeroing) -> table_mma -> gather_add.
// ----------------------------------------------------------------------------

#define DMODEL 512
#define BATCH  32
#define PLEN   2048
#define NV4    (DMODEL / 4)

// g_Ahi/g_Alo rows: [0,2048) pe | [2048,2336) emb2 | [2336,2432) zero pad
#define AROWS   2432
#define A01ROWS 192          // 168 used, pad to 3*64

__device__ float g_T2 [288  * DMODEL];
__device__ float g_Tp [PLEN * DMODEL];
__device__ float g_T01[168  * DMODEL];
__device__ __nv_bfloat16 g_Ahi [AROWS * DMODEL];
__device__ __nv_bfloat16 g_Alo [AROWS * DMODEL];
__device__ __nv_bfloat16 g_A01hi[A01ROWS * 1024];
__device__ __nv_bfloat16 g_A01lo[A01ROWS * 1024];
__device__ __nv_bfloat16 g_Whi[DMODEL * 2048];   // [n][k], K-major rows
__device__ __nv_bfloat16 g_Wlo[DMODEL * 2048];

// ---------------------------------------------------------------- asm helpers
__device__ __forceinline__ uint32_t smem_u32(const void* p) {
    uint32_t a;
    asm("{ .reg .u64 t; cvta.to.shared.u64 t, %1; cvt.u32.u64 %0, t; }"
        : "=r"(a) : "l"(p));
    return a;
}

__device__ __forceinline__ void cp16(uint32_t dst, const void* src) {
    asm volatile("cp.async.cg.shared.global [%0], [%1], 16;"
                 :: "r"(dst), "l"(src));
}
#define CP_COMMIT() asm volatile("cp.async.commit_group;")

__device__ __forceinline__ void ldsm4(uint32_t* r, uint32_t addr) {
    asm volatile("ldmatrix.sync.aligned.m8n8.x4.shared.b16 {%0,%1,%2,%3}, [%4];"
                 : "=r"(r[0]), "=r"(r[1]), "=r"(r[2]), "=r"(r[3]) : "r"(addr));
}

__device__ __forceinline__ void mma16816(float* c, const uint32_t* a, const uint32_t* b) {
    asm volatile(
        "mma.sync.aligned.m16n8k16.row.col.f32.bf16.bf16.f32 "
        "{%0,%1,%2,%3}, {%4,%5,%6,%7}, {%8,%9}, {%0,%1,%2,%3};"
        : "+f"(c[0]), "+f"(c[1]), "+f"(c[2]), "+f"(c[3])
        : "r"(a[0]), "r"(a[1]), "r"(a[2]), "r"(a[3]), "r"(b[0]), "r"(b[1]));
}

// vector float2 reduction (sm_90+): one instruction per contiguous pair
__device__ __forceinline__ void red2(float* p, float x, float y) {
    asm volatile("red.global.add.v2.f32 [%0], {%1, %2};"
                 :: "l"(p), "f"(x), "f"(y) : "memory");
}

__device__ __forceinline__ uint2 split_pack(float4 v) {
    __nv_bfloat16 hx = __float2bfloat16(v.x), hy = __float2bfloat16(v.y);
    __nv_bfloat16 hz = __float2bfloat16(v.z), hw = __float2bfloat16(v.w);
    uint2 p;
    p.x = (uint32_t)__bfloat16_as_ushort(hx) | ((uint32_t)__bfloat16_as_ushort(hy) << 16);
    p.y = (uint32_t)__bfloat16_as_ushort(hz) | ((uint32_t)__bfloat16_as_ushort(hw) << 16);
    return p;
}
__device__ __forceinline__ uint2 split_pack_lo(float4 v) {
    __nv_bfloat16 hx = __float2bfloat16(v.x), hy = __float2bfloat16(v.y);
    __nv_bfloat16 hz = __float2bfloat16(v.z), hw = __float2bfloat16(v.w);
    __nv_bfloat16 lx = __float2bfloat16(v.x - __bfloat162float(hx));
    __nv_bfloat16 ly = __float2bfloat16(v.y - __bfloat162float(hy));
    __nv_bfloat16 lz = __float2bfloat16(v.z - __bfloat162float(hz));
    __nv_bfloat16 lw = __float2bfloat16(v.w - __bfloat162float(hw));
    uint2 p;
    p.x = (uint32_t)__bfloat16_as_ushort(lx) | ((uint32_t)__bfloat16_as_ushort(ly) << 16);
    p.y = (uint32_t)__bfloat16_as_ushort(lz) | ((uint32_t)__bfloat16_as_ushort(lw) << 16);
    return p;
}

// ----------------------------------------------------------------------------
// prep: ONE launch for all conversions + zeroing of accumulator tables.
//  blocks [0,1024)     : conv_W 32x32 transpose tiles -> Whi/Wlo [n][k]
//  blocks [1024,2240)  : conv_A, 2 rows/block -> Ahi/Alo
//  blocks [2240,2432)  : conv_A01, 1 row/block -> A01hi/lo
//  blocks [2432,2745)  : zero tables, branch-free per-table ranges
//     Tp: 256 blocks, T2: 36 blocks, T01: 21 blocks (1024 float4 each)
// ----------------------------------------------------------------------------
#define PREP_GRID (2432 + 256 + 36 + 21)

__global__ __launch_bounds__(256) void prep(
    const float* __restrict__ W,    const float* __restrict__ pe,
    const float* __restrict__ emb2, const float* __restrict__ emb1,
    const float* __restrict__ emb0)
{
    __shared__ float tile[32][33];
    const int bx = blockIdx.x;

    if (bx < 1024) {
        // ---- conv_W: split-transpose W[2048,512] -> [n=512][k=2048]
        const int k0 = (bx & 63) * 32, n0 = (bx >> 6) * 32;
        const int tx = threadIdx.x & 31, ty = threadIdx.x >> 5;
        #pragma unroll
        for (int r = 0; r < 4; r++) {
            int i = ty + 8 * r;
            tile[i][tx] = W[(size_t)(k0 + i) * DMODEL + n0 + tx];
        }
        __syncthreads();
        #pragma unroll
        for (int r = 0; r < 4; r++) {
            int i = ty + 8 * r;                   // n_local
            float v = tile[tx][i];                // k_local = tx
            __nv_bfloat16 h = __float2bfloat16(v);
            __nv_bfloat16 l = __float2bfloat16(v - __bfloat162float(h));
            size_t o = (size_t)(n0 + i) * 2048 + k0 + tx;
            g_Whi[o] = h;
            g_Wlo[o] = l;
        }
    } else if (bx < 2240) {
        // ---- conv_A: rows of pe / emb2 (padded) -> Ahi/Alo
        const int pr = (bx - 1024) * 2 + (threadIdx.x >> 7);
        const int t  = threadIdx.x & 127;
        const float* src = nullptr;
        if (pr < 2048)      { src = pe + (size_t)pr * DMODEL; }
        else                { int r = pr - 2048; if (r < 288) src = emb2 + (size_t)r * DMODEL; }
        float4 v = src ? ((const float4*)src)[t] : make_float4(0.f, 0.f, 0.f, 0.f);
        ((uint2*)g_Ahi)[(size_t)pr * NV4 + t] = split_pack(v);
        ((uint2*)g_Alo)[(size_t)pr * NV4 + t] = split_pack_lo(v);
    } else if (bx < 2432) {
        // ---- conv_A01: row r = concat(emb0[r/24], emb1[r%24]) over K=1024
        const int r = bx - 2240;                  // 0..191
        const int c = threadIdx.x;                // float4 lane 0..255
        float4 v = make_float4(0.f, 0.f, 0.f, 0.f);
        if (r < 168) {
            const int i = r / 24, j = r % 24;
            v = (c < 128) ? ((const float4*)(emb0 + (size_t)i * DMODEL))[c]
                          : ((const float4*)(emb1 + (size_t)j * DMODEL))[c - 128];
        }
        ((uint2*)g_A01hi)[(size_t)r * 256 + c] = split_pack(v);
        ((uint2*)g_A01lo)[(size_t)r * 256 + c] = split_pack_lo(v);
    } else {
        // ---- zero accumulator tables: uniform per-block target, coalesced
        const int bz = bx - 2432;
        const float4 z = make_float4(0.f, 0.f, 0.f, 0.f);
        float4* p;
        if (bz < 256)      p = (float4*)g_Tp  + (size_t)bz * 1024;
        else if (bz < 292) p = (float4*)g_T2  + (size_t)(bz - 256) * 1024;
        else               p = (float4*)g_T01 + (size_t)(bz - 292) * 1024;
        p += threadIdx.x;
        p[0] = z; p[256] = z; p[512] = z; p[768] = z;
    }
}

// ----------------------------------------------------------------------------
// table_mma: uniform split-K/split-term bf16 MMA.
// grid (132, 8): bx = term*44 + unit ; 128 threads; CTA tile 64(M) x 64(N),
// exactly 16 k32 stages (K=512) per CTA. Results via red.global.add.v2.f32
// (tables zeroed in prep). Bias added by term-0 Tp CTAs only.
//  unit  0..31 : Tp  (K-rows 1536..2047 of W)
//  unit 32..37 : T2  (K-rows 1024..1535)
//  unit 38..43 : T01 (h = unit-38: m = h>>1, khalf = h&1 -> K-rows 0..1023)
// ----------------------------------------------------------------------------
#define ROWB   80
#define OPBYTES (64 * ROWB)          // 5120 per operand per stage
#define NSTAGE 3
#define NKS    16

__global__ __launch_bounds__(128) void table_mma(const float* __restrict__ bias)
{
    __shared__ __align__(16) char sm[NSTAGE * 2 * OPBYTES];   // 30720 B
    const uint32_t sbase = smem_u32(sm);

    const int tid = threadIdx.x;
    const int bx = blockIdx.x, by = blockIdx.y;
    const int col0 = by * 64;
    const int term = bx / 44;
    const int unit = bx - term * 44;

    const __nv_bfloat16 *Ahip, *Alop;
    float* C; int M, arow0, astride, koffB, koffA; bool addb = false;
    if (unit < 32) {
        Ahip = g_Ahi;   Alop = g_Alo;   C = g_Tp;  M = 2048;
        arow0 = unit * 64;        astride = 512;  koffB = 1536; koffA = 0;
        addb = (term == 0);
    } else if (unit < 38) {
        Ahip = g_Ahi + (size_t)2048 * DMODEL;
        Alop = g_Alo + (size_t)2048 * DMODEL;
        C = g_T2;  M = 288;
        arow0 = (unit - 32) * 64; astride = 512;  koffB = 1024; koffA = 0;
    } else {
        const int h = unit - 38;                  // 0..5
        Ahip = g_A01hi; Alop = g_A01lo; C = g_T01; M = 168;
        arow0 = (h >> 1) * 64;    astride = 1024;
        koffB = (h & 1) * 512;    koffA = (h & 1) * 512;
    }

    const __nv_bfloat16* Asrc = (term == 2) ? Alop  : Ahip;
    const __nv_bfloat16* Bsrc = (term == 1) ? g_Wlo : g_Whi;

    // per-thread cp.async geometry: rows tid>>2 and +32, quarter q = tid&3
    const int rA = tid >> 2;
    const int q  = tid & 3;
    const uint32_t dA0 = rA * ROWB + q * 16;
    const uint32_t dA1 = (rA + 32) * ROWB + q * 16;
    const __nv_bfloat16* pa0 = Asrc + (size_t)(arow0 + rA) * astride + koffA + q * 8;
    const __nv_bfloat16* pa1 = pa0 + (size_t)32 * astride;
    const __nv_bfloat16* pb0 = Bsrc + (size_t)(col0 + rA) * 2048 + koffB + q * 8;
    const __nv_bfloat16* pb1 = pb0 + (size_t)32 * 2048;

    // warp / lane geometry
    const int wid  = tid >> 5, lane = tid & 31;
    const int wm   = (wid & 1) * 32, wn = (wid >> 1) * 32;
    const int quad = lane >> 3, lr = lane & 7;

    uint32_t offA[2], offB[2];
    #pragma unroll
    for (int mf = 0; mf < 2; mf++)
        offA[mf] = (uint32_t)(wm + mf * 16 + (quad & 1) * 8 + lr) * ROWB + (quad >> 1) * 16;
    #pragma unroll
    for (int nb = 0; nb < 2; nb++)
        offB[nb] = (uint32_t)(wn + nb * 16 + ((quad >> 1) & 1) * 8 + lr) * ROWB + (quad & 1) * 16;

    float acc[2][4][4] = {};

    auto issue = [&](int s) {
        const int k0 = s * 32;
        const uint32_t sA = sbase + (uint32_t)(s % NSTAGE) * (2 * OPBYTES);
        const uint32_t sB = sA + OPBYTES;
        cp16(sA + dA0, pa0 + k0);
        cp16(sA + dA1, pa1 + k0);
        cp16(sB + dA0, pb0 + k0);
        cp16(sB + dA1, pb1 + k0);
        CP_COMMIT();
    };

    issue(0);
    issue(1);

    for (int s = 0; s < NKS; s++) {
        if (s + 2 < NKS) {
            issue(s + 2);
            asm volatile("cp.async.wait_group 2;");
        } else {
            asm volatile("cp.async.wait_group 0;");
        }
        __syncthreads();

        const uint32_t sA = sbase + (uint32_t)(s % NSTAGE) * (2 * OPBYTES);
        const uint32_t sB = sA + OPBYTES;

        #pragma unroll
        for (int kh = 0; kh < 2; kh++) {          // two k16 steps per k32 stage
            uint32_t a[2][4], b[2][4];
            ldsm4(a[0], sA + offA[0] + kh * 32);
            ldsm4(a[1], sA + offA[1] + kh * 32);
            ldsm4(b[0], sB + offB[0] + kh * 32);
            ldsm4(b[1], sB + offB[1] + kh * 32);
            #pragma unroll
            for (int mf = 0; mf < 2; mf++) {
                mma16816(acc[mf][0], a[mf], &b[0][0]);
                mma16816(acc[mf][1], a[mf], &b[0][2]);
                mma16816(acc[mf][2], a[mf], &b[1][0]);
                mma16816(acc[mf][3], a[mf], &b[1][2]);
            }
        }
        __syncthreads();
    }

    // ---- epilogue: vector reductions; bias once via term-0 Tp CTAs
    const int erow = lane >> 2;
    const int ecol = (lane & 3) * 2;

    float2 bb[4];
    #pragma unroll
    for (int nf = 0; nf < 4; nf++) {
        if (addb) {
            const int n = col0 + wn + nf * 8 + ecol;
            bb[nf].x = bias[n];
            bb[nf].y = bias[n + 1];
        } else {
            bb[nf].x = 0.f; bb[nf].y = 0.f;
        }
    }

    #pragma unroll
    for (int mf = 0; mf < 2; mf++) {
        const int m0 = arow0 + wm + mf * 16 + erow;
        #pragma unroll
        for (int nf = 0; nf < 4; nf++) {
            const int n = col0 + wn + nf * 8 + ecol;
            if (m0 < M)
                red2(&C[(size_t)m0 * DMODEL + n],
                     acc[mf][nf][0] + bb[nf].x, acc[mf][nf][1] + bb[nf].y);
            if (m0 + 8 < M)
                red2(&C[(size_t)(m0 + 8) * DMODEL + n],
                     acc[mf][nf][2] + bb[nf].x, acc[mf][nf][3] + bb[nf].y);
        }
    }
}

// ----------------------------------------------------------------------------
// gather_add: out = T01 + T2 + Tp.  grid (2048, 2), 128 threads.
// ----------------------------------------------------------------------------
__global__ __launch_bounds__(128) void gather_add(
    const int* __restrict__ in0, const int* __restrict__ tg0,
    const int* __restrict__ in1, const int* __restrict__ tg1,
    const int* __restrict__ in2, const int* __restrict__ tg2,
    float* __restrict__ out)
{
    const int l = blockIdx.x, o = blockIdx.y, t = threadIdx.x;

    __shared__ int sidx[3][BATCH];
    if (t < 96) {
        int which = t >> 5, b = t & 31;
        const int* p = (which == 0) ? (o ? tg0 : in0)
                     : (which == 1) ? (o ? tg1 : in1)
                                    : (o ? tg2 : in2);
        sidx[which][b] = p[b * PLEN + l];
    }
    __syncthreads();

    const float4* __restrict__ T01 = (const float4*)g_T01;
    const float4* __restrict__ T2  = (const float4*)g_T2;
    const float4 tp = ((const float4*)g_Tp)[l * NV4 + t];

    float4* o4 = (float4*)out + ((size_t)o * BATCH * PLEN + l) * NV4 + t;

    #pragma unroll 8
    for (int b = 0; b < BATCH; b++) {
        const int i01 = sidx[0][b] * 24 + sidx[1][b];
        const int i2  = sidx[2][b];
        float4 a = T01[i01 * NV4 + t];
        float4 d = T2 [i2  * NV4 + t];
        float4 v;
        v.x = tp.x + a.x + d.x;
        v.y = tp.y + a.y + d.y;
        v.z = tp.z + a.z + d.z;
        v.w = tp.w + a.w + d.w;
        __stcs(o4 + (size_t)b * PLEN * NV4, v);
    }
}

// ----------------------------------------------------------------------------
// Launch. Inputs (metadata order):
//  0..5: in0,tg0,in1,tg1,in2,tg2 int32 [32,2048]
//  6:emb0[7,512] 7:emb1[24,512] 8:emb2[288,512] 9:pe[4096,512]
//  10:W[2048,512] 11:b[512]       output: float32 [2,32,2048,512]
// ----------------------------------------------------------------------------
extern "C" void kernel_launch(void* const* d_in, const int* in_sizes, int n_in,
                              void* d_out, int out_size)
{
    const int*   in0  = (const int*)  d_in[0];
    const int*   tg0  = (const int*)  d_in[1];
    const int*   in1  = (const int*)  d_in[2];
    const int*   tg1  = (const int*)  d_in[3];
    const int*   in2  = (const int*)  d_in[4];
    const int*   tg2  = (const int*)  d_in[5];
    const float* emb0 = (const float*)d_in[6];
    const float* emb1 = (const float*)d_in[7];
    const float* emb2 = (const float*)d_in[8];
    const float* pe   = (const float*)d_in[9];
    const float* W    = (const float*)d_in[10];
    const float* bias = (const float*)d_in[11];
    float* out = (float*)d_out;

    prep<<<PREP_GRID, 256>>>(W, pe, emb2, emb1, emb0);
    table_mma<<<dim3(132, 8), 128>>>(bias);
    gather_add<<<dim3(PLEN, 2), 128>>>(in0, tg0, in1, tg1, in2, tg2, out);
}

// round 14
// speedup vs baseline: 1.2137x; 1.0118x over previous
#include <cuda_runtime.h>
#include <cuda_bf16.h>
#include <cstdint>

// ----------------------------------------------------------------------------
// TemporalEmbedding via precomputed tables.
//   out[o,b,l,:] = T01[i0*24+i1] + T2[i2] + Tp[l]
// Tables via mma.sync bf16 split-precision (3-term Markidis):
//   A@B ~= Ahi@Bhi + Ahi@Blo + Alo@Bhi   (fp32 accumulate)
// All three terms fused per CTA (uniform 48 k32-stages = 16 k-groups x 3
// terms, sharing the 4 distinct tiles Ahi/Alo/Whi/Wlo per k-group).
// Tp/T2 written with plain stores (register accumulation); only T01's two
// K-half CTAs combine via red.global.add.v2.f32 into a zeroed table.
// Launch order: prep -> table_mma -> gather_add.
// ----------------------------------------------------------------------------

#define DMODEL 512
#define BATCH  32
#define PLEN   2048
#define NV4    (DMODEL / 4)

// g_Ahi/g_Alo rows: [0,2048) pe | [2048,2336) emb2 | [2336,2432) zero pad
#define AROWS   2432
#define A01ROWS 192          // 168 used, pad to 3*64

__device__ float g_T2 [288  * DMODEL];
__device__ float g_Tp [PLEN * DMODEL];
__device__ float g_T01[168  * DMODEL];
__device__ __nv_bfloat16 g_Ahi [AROWS * DMODEL];
__device__ __nv_bfloat16 g_Alo [AROWS * DMODEL];
__device__ __nv_bfloat16 g_A01hi[A01ROWS * 1024];
__device__ __nv_bfloat16 g_A01lo[A01ROWS * 1024];
__device__ __nv_bfloat16 g_Whi[DMODEL * 2048];   // [n][k], K-major rows
__device__ __nv_bfloat16 g_Wlo[DMODEL * 2048];

// ---------------------------------------------------------------- asm helpers
__device__ __forceinline__ uint32_t smem_u32(const void* p) {
    uint32_t a;
    asm("{ .reg .u64 t; cvta.to.shared.u64 t, %1; cvt.u32.u64 %0, t; }"
        : "=r"(a) : "l"(p));
    return a;
}

__device__ __forceinline__ void cp16(uint32_t dst, const void* src) {
    asm volatile("cp.async.cg.shared.global [%0], [%1], 16;"
                 :: "r"(dst), "l"(src));
}
#define CP_COMMIT() asm volatile("cp.async.commit_group;")

__device__ __forceinline__ void ldsm4(uint32_t* r, uint32_t addr) {
    asm volatile("ldmatrix.sync.aligned.m8n8.x4.shared.b16 {%0,%1,%2,%3}, [%4];"
                 : "=r"(r[0]), "=r"(r[1]), "=r"(r[2]), "=r"(r[3]) : "r"(addr));
}

__device__ __forceinline__ void mma16816(float* c, const uint32_t* a, const uint32_t* b) {
    asm volatile(
        "mma.sync.aligned.m16n8k16.row.col.f32.bf16.bf16.f32 "
        "{%0,%1,%2,%3}, {%4,%5,%6,%7}, {%8,%9}, {%0,%1,%2,%3};"
        : "+f"(c[0]), "+f"(c[1]), "+f"(c[2]), "+f"(c[3])
        : "r"(a[0]), "r"(a[1]), "r"(a[2]), "r"(a[3]), "r"(b[0]), "r"(b[1]));
}

// vector float2 reduction (sm_90+)
__device__ __forceinline__ void red2(float* p, float x, float y) {
    asm volatile("red.global.add.v2.f32 [%0], {%1, %2};"
                 :: "l"(p), "f"(x), "f"(y) : "memory");
}

__device__ __forceinline__ uint2 split_pack(float4 v) {
    __nv_bfloat16 hx = __float2bfloat16(v.x), hy = __float2bfloat16(v.y);
    __nv_bfloat16 hz = __float2bfloat16(v.z), hw = __float2bfloat16(v.w);
    uint2 p;
    p.x = (uint32_t)__bfloat16_as_ushort(hx) | ((uint32_t)__bfloat16_as_ushort(hy) << 16);
    p.y = (uint32_t)__bfloat16_as_ushort(hz) | ((uint32_t)__bfloat16_as_ushort(hw) << 16);
    return p;
}
__device__ __forceinline__ uint2 split_pack_lo(float4 v) {
    __nv_bfloat16 hx = __float2bfloat16(v.x), hy = __float2bfloat16(v.y);
    __nv_bfloat16 hz = __float2bfloat16(v.z), hw = __float2bfloat16(v.w);
    __nv_bfloat16 lx = __float2bfloat16(v.x - __bfloat162float(hx));
    __nv_bfloat16 ly = __float2bfloat16(v.y - __bfloat162float(hy));
    __nv_bfloat16 lz = __float2bfloat16(v.z - __bfloat162float(hz));
    __nv_bfloat16 lw = __float2bfloat16(v.w - __bfloat162float(hw));
    uint2 p;
    p.x = (uint32_t)__bfloat16_as_ushort(lx) | ((uint32_t)__bfloat16_as_ushort(ly) << 16);
    p.y = (uint32_t)__bfloat16_as_ushort(lz) | ((uint32_t)__bfloat16_as_ushort(lw) << 16);
    return p;
}

// ----------------------------------------------------------------------------
// prep: conversions + zeroing of T01 only (Tp/T2 are plain-stored now).
//  blocks [0,1024)     : conv_W 32x32 transpose tiles -> Whi/Wlo [n][k]
//  blocks [1024,2240)  : conv_A, 2 rows/block -> Ahi/Alo
//  blocks [2240,2432)  : conv_A01, 1 row/block -> A01hi/lo
//  blocks [2432,2453)  : zero g_T01 (21 blocks x 1024 float4)
// ----------------------------------------------------------------------------
#define PREP_GRID (2432 + 21)

__global__ __launch_bounds__(256) void prep(
    const float* __restrict__ W,    const float* __restrict__ pe,
    const float* __restrict__ emb2, const float* __restrict__ emb1,
    const float* __restrict__ emb0)
{
    __shared__ float tile[32][33];
    const int bx = blockIdx.x;

    if (bx < 1024) {
        // ---- conv_W: split-transpose W[2048,512] -> [n=512][k=2048]
        const int k0 = (bx & 63) * 32, n0 = (bx >> 6) * 32;
        const int tx = threadIdx.x & 31, ty = threadIdx.x >> 5;
        #pragma unroll
        for (int r = 0; r < 4; r++) {
            int i = ty + 8 * r;
            tile[i][tx] = W[(size_t)(k0 + i) * DMODEL + n0 + tx];
        }
        __syncthreads();
        #pragma unroll
        for (int r = 0; r < 4; r++) {
            int i = ty + 8 * r;                   // n_local
            float v = tile[tx][i];                // k_local = tx
            __nv_bfloat16 h = __float2bfloat16(v);
            __nv_bfloat16 l = __float2bfloat16(v - __bfloat162float(h));
            size_t o = (size_t)(n0 + i) * 2048 + k0 + tx;
            g_Whi[o] = h;
            g_Wlo[o] = l;
        }
    } else if (bx < 2240) {
        // ---- conv_A: rows of pe / emb2 (padded) -> Ahi/Alo
        const int pr = (bx - 1024) * 2 + (threadIdx.x >> 7);
        const int t  = threadIdx.x & 127;
        const float* src = nullptr;
        if (pr < 2048)      { src = pe + (size_t)pr * DMODEL; }
        else                { int r = pr - 2048; if (r < 288) src = emb2 + (size_t)r * DMODEL; }
        float4 v = src ? ((const float4*)src)[t] : make_float4(0.f, 0.f, 0.f, 0.f);
        ((uint2*)g_Ahi)[(size_t)pr * NV4 + t] = split_pack(v);
        ((uint2*)g_Alo)[(size_t)pr * NV4 + t] = split_pack_lo(v);
    } else if (bx < 2432) {
        // ---- conv_A01: row r = concat(emb0[r/24], emb1[r%24]) over K=1024
        const int r = bx - 2240;                  // 0..191
        const int c = threadIdx.x;                // float4 lane 0..255
        float4 v = make_float4(0.f, 0.f, 0.f, 0.f);
        if (r < 168) {
            const int i = r / 24, j = r % 24;
            v = (c < 128) ? ((const float4*)(emb0 + (size_t)i * DMODEL))[c]
                          : ((const float4*)(emb1 + (size_t)j * DMODEL))[c - 128];
        }
        ((uint2*)g_A01hi)[(size_t)r * 256 + c] = split_pack(v);
        ((uint2*)g_A01lo)[(size_t)r * 256 + c] = split_pack_lo(v);
    } else {
        // ---- zero T01 (21 blocks x 1024 float4 = 21504)
        const int bz = bx - 2432;
        const float4 z = make_float4(0.f, 0.f, 0.f, 0.f);
        float4* p = (float4*)g_T01 + (size_t)bz * 1024 + threadIdx.x;
        p[0] = z; p[256] = z; p[512] = z; p[768] = z;
    }
}

// ----------------------------------------------------------------------------
// table_mma: term-fused uniform bf16 MMA.
// grid (44, 8), 128 threads. CTA tile 64(M) x 64(N). 16 k-groups; each group
// loads 4 tiles (Ahi/Alo/Whi/Wlo, one per warp) and runs 3 terms = 48 virtual
// k32 stages. Double-buffered cp.async.
//  unit  0..31 : Tp  (K-rows 1536..2047 of W) -> plain store + bias
//  unit 32..37 : T2  (K-rows 1024..1535)      -> plain store
//  unit 38..43 : T01 (h: m-tile h>>1, K-half h&1) -> red2 into zeroed table
// ----------------------------------------------------------------------------
#define ROWB  80
#define TILEB (64 * ROWB)        // 5120 per tile (4KB data + pad)
#define KGRP  (4 * TILEB)        // 20480 per k-group buffer
#define NKG   16

__global__ __launch_bounds__(128) void table_mma(const float* __restrict__ bias)
{
    __shared__ __align__(16) char sm[2 * KGRP];   // 40960 B
    const uint32_t sbase = smem_u32(sm);

    const int tid = threadIdx.x;
    const int bx = blockIdx.x, by = blockIdx.y;
    const int col0 = by * 64;

    const __nv_bfloat16 *Ahip, *Alop;
    float* C; int M, arow0, astride, koffB, koffA; bool addb = false, isT01 = false;
    if (bx < 32) {
        Ahip = g_Ahi;   Alop = g_Alo;   C = g_Tp;  M = 2048;
        arow0 = bx * 64;        astride = 512;  koffB = 1536; koffA = 0;
        addb = true;
    } else if (bx < 38) {
        Ahip = g_Ahi + (size_t)2048 * DMODEL;
        Alop = g_Alo + (size_t)2048 * DMODEL;
        C = g_T2;  M = 288;
        arow0 = (bx - 32) * 64; astride = 512;  koffB = 1024; koffA = 0;
    } else {
        const int h = bx - 38;                    // 0..5
        Ahip = g_A01hi; Alop = g_A01lo; C = g_T01; M = 168;
        arow0 = (h >> 1) * 64;    astride = 1024;
        koffB = (h & 1) * 512;    koffA = (h & 1) * 512;
        isT01 = true;
    }

    // ---- loader geometry: warp w loads tile w (0:Ahi 1:Alo 2:Whi 3:Wlo)
    const int wid  = tid >> 5, lane = tid & 31;
    const int lrow = lane >> 2;                   // 0..7
    const int lq   = lane & 3;                    // 16B quarter
    const __nv_bfloat16* wsrc;
    int wrs, wrow0, wkoff;
    if (wid == 0)      { wsrc = Ahip;  wrs = astride; wrow0 = arow0; wkoff = koffA; }
    else if (wid == 1) { wsrc = Alop;  wrs = astride; wrow0 = arow0; wkoff = koffA; }
    else if (wid == 2) { wsrc = g_Whi; wrs = 2048;    wrow0 = col0;  wkoff = koffB; }
    else               { wsrc = g_Wlo; wrs = 2048;    wrow0 = col0;  wkoff = koffB; }
    const __nv_bfloat16* p0 = wsrc + (size_t)(wrow0 + lrow) * wrs + wkoff + lq * 8;
    const uint32_t d0 = (uint32_t)wid * TILEB + lrow * ROWB + lq * 16;
    const size_t rs8 = (size_t)wrs * 8;

    // ---- compute geometry: 2x2 warps, each 32m x 32n
    const int wm   = (wid & 1) * 32, wn = (wid >> 1) * 32;
    const int quad = lane >> 3, lr = lane & 7;

    uint32_t offA[2], offB[2];
    #pragma unroll
    for (int mf = 0; mf < 2; mf++)
        offA[mf] = (uint32_t)(wm + mf * 16 + (quad & 1) * 8 + lr) * ROWB + (quad >> 1) * 16;
    #pragma unroll
    for (int nb = 0; nb < 2; nb++)
        offB[nb] = (uint32_t)(wn + nb * 16 + ((quad >> 1) & 1) * 8 + lr) * ROWB + (quad & 1) * 16;

    float acc[2][4][4] = {};

    auto issue = [&](int k) {
        const uint32_t dst = sbase + (uint32_t)(k & 1) * KGRP + d0;
        const __nv_bfloat16* src = p0 + (size_t)k * 32;
        #pragma unroll
        for (int j = 0; j < 8; j++)
            cp16(dst + j * (8 * ROWB), src + j * rs8);
        CP_COMMIT();
    };

    issue(0);

    for (int k = 0; k < NKG; k++) {
        if (k + 1 < NKG) {
            issue(k + 1);
            asm volatile("cp.async.wait_group 1;");
        } else {
            asm volatile("cp.async.wait_group 0;");
        }
        __syncthreads();

        const uint32_t base = sbase + (uint32_t)(k & 1) * KGRP;
        const uint32_t bAhi = base;
        const uint32_t bAlo = base + TILEB;
        const uint32_t bWhi = base + 2 * TILEB;
        const uint32_t bWlo = base + 3 * TILEB;

        #pragma unroll
        for (int kh = 0; kh < 2; kh++) {          // two k16 per k32 group
            uint32_t ah[2][4], al[2][4], bfr[2][4];
            ldsm4(ah[0], bAhi + offA[0] + kh * 32);
            ldsm4(ah[1], bAhi + offA[1] + kh * 32);
            ldsm4(al[0], bAlo + offA[0] + kh * 32);
            ldsm4(al[1], bAlo + offA[1] + kh * 32);
            ldsm4(bfr[0], bWhi + offB[0] + kh * 32);
            ldsm4(bfr[1], bWhi + offB[1] + kh * 32);
            #pragma unroll
            for (int mf = 0; mf < 2; mf++) {      // Ahi x Whi
                mma16816(acc[mf][0], ah[mf], &bfr[0][0]);
                mma16816(acc[mf][1], ah[mf], &bfr[0][2]);
                mma16816(acc[mf][2], ah[mf], &bfr[1][0]);
                mma16816(acc[mf][3], ah[mf], &bfr[1][2]);
            }
            #pragma unroll
            for (int mf = 0; mf < 2; mf++) {      // Alo x Whi
                mma16816(acc[mf][0], al[mf], &bfr[0][0]);
                mma16816(acc[mf][1], al[mf], &bfr[0][2]);
                mma16816(acc[mf][2], al[mf], &bfr[1][0]);
                mma16816(acc[mf][3], al[mf], &bfr[1][2]);
            }
            ldsm4(bfr[0], bWlo + offB[0] + kh * 32);
            ldsm4(bfr[1], bWlo + offB[1] + kh * 32);
            #pragma unroll
            for (int mf = 0; mf < 2; mf++) {      // Ahi x Wlo
                mma16816(acc[mf][0], ah[mf], &bfr[0][0]);
                mma16816(acc[mf][1], ah[mf], &bfr[0][2]);
                mma16816(acc[mf][2], ah[mf], &bfr[1][0]);
                mma16816(acc[mf][3], ah[mf], &bfr[1][2]);
            }
        }
        __syncthreads();
    }

    // ---- epilogue
    const int erow = lane >> 2;
    const int ecol = (lane & 3) * 2;

    float2 bb[4];
    #pragma unroll
    for (int nf = 0; nf < 4; nf++) {
        if (addb) {
            const int n = col0 + wn + nf * 8 + ecol;
            bb[nf].x = bias[n];
            bb[nf].y = bias[n + 1];
        } else {
            bb[nf].x = 0.f; bb[nf].y = 0.f;
        }
    }

    #pragma unroll
    for (int mf = 0; mf < 2; mf++) {
        const int m0 = arow0 + wm + mf * 16 + erow;
        #pragma unroll
        for (int nf = 0; nf < 4; nf++) {
            const int n = col0 + wn + nf * 8 + ecol;
            if (isT01) {
                if (m0 < M)
                    red2(&C[(size_t)m0 * DMODEL + n],
                         acc[mf][nf][0], acc[mf][nf][1]);
                if (m0 + 8 < M)
                    red2(&C[(size_t)(m0 + 8) * DMODEL + n],
                         acc[mf][nf][2], acc[mf][nf][3]);
            } else {
                if (m0 < M) {
                    float2 v = make_float2(acc[mf][nf][0] + bb[nf].x,
                                           acc[mf][nf][1] + bb[nf].y);
                    *(float2*)&C[(size_t)m0 * DMODEL + n] = v;
                }
                if (m0 + 8 < M) {
                    float2 v = make_float2(acc[mf][nf][2] + bb[nf].x,
                                           acc[mf][nf][3] + bb[nf].y);
                    *(float2*)&C[(size_t)(m0 + 8) * DMODEL + n] = v;
                }
            }
        }
    }
}

// ----------------------------------------------------------------------------
// gather_add: out = T01 + T2 + Tp.  grid (2048, 2), 128 threads.
// ----------------------------------------------------------------------------
__global__ __launch_bounds__(128) void gather_add(
    const int* __restrict__ in0, const int* __restrict__ tg0,
    const int* __restrict__ in1, const int* __restrict__ tg1,
    const int* __restrict__ in2, const int* __restrict__ tg2,
    float* __restrict__ out)
{
    const int l = blockIdx.x, o = blockIdx.y, t = threadIdx.x;

    __shared__ int sidx[3][BATCH];
    if (t < 96) {
        int which = t >> 5, b = t & 31;
        const int* p = (which == 0) ? (o ? tg0 : in0)
                     : (which == 1) ? (o ? tg1 : in1)
                                    : (o ? tg2 : in2);
        sidx[which][b] = p[b * PLEN + l];
    }
    __syncthreads();

    const float4* __restrict__ T01 = (const float4*)g_T01;
    const float4* __restrict__ T2  = (const float4*)g_T2;
    const float4 tp = ((const float4*)g_Tp)[l * NV4 + t];

    float4* o4 = (float4*)out + ((size_t)o * BATCH * PLEN + l) * NV4 + t;

    #pragma unroll 8
    for (int b = 0; b < BATCH; b++) {
        const int i01 = sidx[0][b] * 24 + sidx[1][b];
        const int i2  = sidx[2][b];
        float4 a = T01[i01 * NV4 + t];
        float4 d = T2 [i2  * NV4 + t];
        float4 v;
        v.x = tp.x + a.x + d.x;
        v.y = tp.y + a.y + d.y;
        v.z = tp.z + a.z + d.z;
        v.w = tp.w + a.w + d.w;
        __stcs(o4 + (size_t)b * PLEN * NV4, v);
    }
}

// ----------------------------------------------------------------------------
// Launch. Inputs (metadata order):
//  0..5: in0,tg0,in1,tg1,in2,tg2 int32 [32,2048]
//  6:emb0[7,512] 7:emb1[24,512] 8:emb2[288,512] 9:pe[4096,512]
//  10:W[2048,512] 11:b[512]       output: float32 [2,32,2048,512]
// ----------------------------------------------------------------------------
extern "C" void kernel_launch(void* const* d_in, const int* in_sizes, int n_in,
                              void* d_out, int out_size)
{
    const int*   in0  = (const int*)  d_in[0];
    const int*   tg0  = (const int*)  d_in[1];
    const int*   in1  = (const int*)  d_in[2];
    const int*   tg1  = (const int*)  d_in[3];
    const int*   in2  = (const int*)  d_in[4];
    const int*   tg2  = (const int*)  d_in[5];
    const float* emb0 = (const float*)d_in[6];
    const float* emb1 = (const float*)d_in[7];
    const float* emb2 = (const float*)d_in[8];
    const float* pe   = (const float*)d_in[9];
    const float* W    = (const float*)d_in[10];
    const float* bias = (const float*)d_in[11];
    float* out = (float*)d_out;

    prep<<<PREP_GRID, 256>>>(W, pe, emb2, emb1, emb0);
    table_mma<<<dim3(44, 8), 128>>>(bias);
    gather_add<<<dim3(PLEN, 2), 128>>>(in0, tg0, in1, tg1, in2, tg2, out);
}